// round 7
// baseline (speedup 1.0000x reference)
#include <cuda_runtime.h>
#include <math_constants.h>
#include <cstdint>

#define NB 32
#define NC 256
#define HW 1024
#define NRP 16          // row-partial slices (8 j-blocks x 2 wn)
#define NCP 32          // col-partial slices (8 i-blocks x 4 wm)
#define KC 32           // K per chunk
#define NCH (NC / KC)   // 8 chunks

static __device__ __constant__ float c_invT = 14.2857142857142857f; // 1/0.07

__device__ float g_L[(size_t)NB * HW * HW];
__device__ float g_rmax[NB * HW];
__device__ float g_rinv[NB * HW];
__device__ float g_cmax[NB * HW];
__device__ float g_cinv[NB * HW];
__device__ float g_prm[(size_t)NRP * NB * HW];
__device__ float g_prs[(size_t)NRP * NB * HW];
__device__ float g_pcm[(size_t)NCP * NB * HW];
__device__ float g_pcs[(size_t)NCP * NB * HW];

// ---- helpers --------------------------------------------------------------
__device__ __forceinline__ float tf32_rna(float x) {
    uint32_t r;
    asm("cvt.rna.tf32.f32 %0, %1;" : "=r"(r) : "f"(x));
    return __uint_as_float(r);
}
__device__ __forceinline__ uint32_t smem_u32(const void* p) {
    uint32_t a;
    asm("{ .reg .u64 t; cvta.to.shared.u64 t, %1; cvt.u32.u64 %0, t; }"
        : "=r"(a) : "l"(p));
    return a;
}
__device__ __forceinline__ void cp16(uint32_t sdst, const float* gsrc) {
    asm volatile("cp.async.cg.shared.global [%0], [%1], 16;"
                 :: "r"(sdst), "l"(gsrc) : "memory");
}
__device__ __forceinline__ void cp_commit() {
    asm volatile("cp.async.commit_group;" ::: "memory");
}
template <int N>
__device__ __forceinline__ void cp_wait() {
    asm volatile("cp.async.wait_group %0;" :: "n"(N) : "memory");
}
__device__ __forceinline__ void mma_tf32(float c[4], const uint32_t a[4],
                                         const uint32_t b[2]) {
    asm volatile(
        "mma.sync.aligned.m16n8k8.row.col.f32.tf32.tf32.f32 "
        "{%0,%1,%2,%3}, {%4,%5,%6,%7}, {%8,%9}, {%0,%1,%2,%3};"
        : "+f"(c[0]), "+f"(c[1]), "+f"(c[2]), "+f"(c[3])
        : "r"(a[0]), "r"(a[1]), "r"(a[2]), "r"(a[3]), "r"(b[0]), "r"(b[1]));
}

// ---------------------------------------------------------------------------
// Fused GEMM: loads raw features, splits to tf32 hi/lo in registers,
// runs the 3-term split on mma.sync, stores L + fused partial softmax stats.
//
// Smem per stage: A tile 32x128 f32 + B tile 32x128 f32 = 32KB.
// XOR swizzle: float f of row k stored at block (f>>3)^(k&3), keeps both the
// cp.async stores and the fragment-gather LDS.32s conflict-free.
// ---------------------------------------------------------------------------
#define TILE_F (KC * 128)          // 4096 floats
#define STG_F (2 * TILE_F)         // 8192 floats = 32KB
#define GEMM_SMEM (2 * STG_F * 4)  // 65536 bytes

__device__ __forceinline__ void copy_chunk(uint32_t sbase, const float* gA,
                                           const float* gB, int t) {
#pragma unroll
    for (int s = 0; s < 4; s++) {
        int idx = t + s * 256;          // 0..1023
        int k   = idx >> 5;             // 0..31
        int q4  = idx & 31;             // 16B quad within row
        uint32_t sf = ((((q4 >> 1) ^ (k & 3)) << 3) | ((q4 & 1) << 2));
        cp16(sbase + (uint32_t)(k * 128 + sf) * 4, gA + (size_t)k * HW + q4 * 4);
        cp16(sbase + (uint32_t)(TILE_F + k * 128 + sf) * 4,
             gB + (size_t)k * HW + q4 * 4);
    }
    cp_commit();
}

__global__ void __launch_bounds__(256) gemm_fused_kernel(
    const float* __restrict__ A, const float* __restrict__ Bf) {
    extern __shared__ float sm[];
    uint32_t sbase = smem_u32(sm);
    int b  = blockIdx.z;
    int j0 = blockIdx.x * 128;
    int i0 = blockIdx.y * 128;
    int t    = threadIdx.x;
    int wid  = t >> 5;
    int lane = t & 31;
    int wm   = wid >> 1;           // 0..3
    int wn   = wid & 1;            // 0..1
    int g    = lane >> 2;
    int tig  = lane & 3;

    // GEMM-A = feature_B[b][k][i0..], GEMM-B = feature_A[b][k][j0..] (natural j)
    const float* gAb = Bf + (size_t)b * NC * HW + i0;
    const float* gBb = A + (size_t)b * NC * HW + j0;

    float acc[2][8][4];
#pragma unroll
    for (int m = 0; m < 2; m++)
#pragma unroll
        for (int n = 0; n < 8; n++)
#pragma unroll
            for (int r = 0; r < 4; r++) acc[m][n][r] = 0.0f;

    copy_chunk(sbase, gAb, gBb, t);

    for (int c = 0; c < NCH; c++) {
        int stage = c & 1;
        if (c + 1 < NCH) {
            int ns = (c + 1) & 1;
            copy_chunk(sbase + ns * STG_F * 4,
                       gAb + (size_t)(c + 1) * KC * HW,
                       gBb + (size_t)(c + 1) * KC * HW, t);
            cp_wait<1>();
        } else {
            cp_wait<0>();
        }
        __syncthreads();

        const float* sA = sm + stage * STG_F;
        const float* sB = sA + TILE_F;
#pragma unroll
        for (int kt = 0; kt < 4; kt++) {
            uint32_t ahi[2][4], alo[2][4];
#pragma unroll
            for (int m = 0; m < 2; m++)
#pragma unroll
                for (int r = 0; r < 4; r++) {
                    int k   = kt * 8 + tig + 4 * (r >> 1);
                    int blk = (wm * 4 + m * 2 + (r & 1)) ^ tig;
                    float v = sA[k * 128 + blk * 8 + g];
                    float hi = tf32_rna(v);
                    ahi[m][r] = __float_as_uint(hi);
                    alo[m][r] = __float_as_uint(tf32_rna(v - hi));
                }
            uint32_t bhi[8][2], blo[8][2];
#pragma unroll
            for (int n = 0; n < 8; n++)
#pragma unroll
                for (int r = 0; r < 2; r++) {
                    int k   = kt * 8 + tig + 4 * r;
                    int blk = (wn * 8 + n) ^ tig;
                    float v = sB[k * 128 + blk * 8 + g];
                    float hi = tf32_rna(v);
                    bhi[n][r] = __float_as_uint(hi);
                    blo[n][r] = __float_as_uint(tf32_rna(v - hi));
                }
#pragma unroll
            for (int m = 0; m < 2; m++)
#pragma unroll
                for (int n = 0; n < 8; n++) {
                    mma_tf32(acc[m][n], ahi[m], bhi[n]);
                    mma_tf32(acc[m][n], ahi[m], blo[n]);
                    mma_tf32(acc[m][n], alo[m], bhi[n]);
                }
        }
        __syncthreads();
    }

    // ---- scale by 1/T (was folded into operands before) ----
    const float invT = c_invT;
#pragma unroll
    for (int m = 0; m < 2; m++)
#pragma unroll
        for (int n = 0; n < 8; n++)
#pragma unroll
            for (int r = 0; r < 4; r++) acc[m][n][r] *= invT;

    // ---- store L tile ----
    float* Lp = g_L + (size_t)b * HW * HW;
#pragma unroll
    for (int m = 0; m < 2; m++) {
        int row0 = i0 + (wm * 2 + m) * 16 + g;
#pragma unroll
        for (int n = 0; n < 8; n++) {
            int col = j0 + (wn * 8 + n) * 8 + tig * 2;
            *(float2*)(Lp + (size_t)row0 * HW + col) =
                make_float2(acc[m][n][0], acc[m][n][1]);
            *(float2*)(Lp + (size_t)(row0 + 8) * HW + col) =
                make_float2(acc[m][n][2], acc[m][n][3]);
        }
    }

    // ---- fused row partials (over this warp's 64 j's) ----
    int rslice = blockIdx.x * 2 + wn;       // 0..15
#pragma unroll
    for (int m = 0; m < 2; m++)
#pragma unroll
        for (int rp = 0; rp < 2; rp++) {
            float rm = -CUDART_INF_F;
#pragma unroll
            for (int n = 0; n < 8; n++)
                rm = fmaxf(rm, fmaxf(acc[m][n][rp * 2], acc[m][n][rp * 2 + 1]));
            rm = fmaxf(rm, __shfl_xor_sync(0xFFFFFFFFu, rm, 1));
            rm = fmaxf(rm, __shfl_xor_sync(0xFFFFFFFFu, rm, 2));
            float rs = 0.0f;
#pragma unroll
            for (int n = 0; n < 8; n++)
                rs += __expf(acc[m][n][rp * 2] - rm) +
                      __expf(acc[m][n][rp * 2 + 1] - rm);
            rs += __shfl_xor_sync(0xFFFFFFFFu, rs, 1);
            rs += __shfl_xor_sync(0xFFFFFFFFu, rs, 2);
            if (tig == 0) {
                int i = i0 + wm * 32 + m * 16 + rp * 8 + g;
                size_t idx = (size_t)rslice * NB * HW + b * HW + i;
                g_prm[idx] = rm;
                g_prs[idx] = rs;
            }
        }

    // ---- fused col partials (over this warp's 32 i's) ----
    int cslice = blockIdx.y * 4 + wm;       // 0..31
#pragma unroll
    for (int n = 0; n < 8; n++)
#pragma unroll
        for (int q = 0; q < 2; q++) {
            float cm = fmaxf(fmaxf(acc[0][n][q], acc[0][n][2 + q]),
                             fmaxf(acc[1][n][q], acc[1][n][2 + q]));
            cm = fmaxf(cm, __shfl_xor_sync(0xFFFFFFFFu, cm, 4));
            cm = fmaxf(cm, __shfl_xor_sync(0xFFFFFFFFu, cm, 8));
            cm = fmaxf(cm, __shfl_xor_sync(0xFFFFFFFFu, cm, 16));
            float cs = __expf(acc[0][n][q] - cm) + __expf(acc[0][n][2 + q] - cm) +
                       __expf(acc[1][n][q] - cm) + __expf(acc[1][n][2 + q] - cm);
            cs += __shfl_xor_sync(0xFFFFFFFFu, cs, 4);
            cs += __shfl_xor_sync(0xFFFFFFFFu, cs, 8);
            cs += __shfl_xor_sync(0xFFFFFFFFu, cs, 16);
            if (g == 0) {
                int j = j0 + wn * 64 + n * 8 + tig * 2 + q;
                size_t idx = (size_t)cslice * NB * HW + b * HW + j;
                g_pcm[idx] = cm;
                g_pcs[idx] = cs;
            }
        }
}

// ---------------------------------------------------------------------------
// Combine kernel: blockIdx.y==0 -> row partials (16), ==1 -> col partials (32)
// ---------------------------------------------------------------------------
__global__ void combine_kernel() {
    int idx = blockIdx.x * 256 + threadIdx.x;   // b*HW + (i or j)
    if (idx >= NB * HW) return;
    if (blockIdx.y == 0) {
        float m = -CUDART_INF_F;
        float mv[NRP], sv[NRP];
#pragma unroll
        for (int p = 0; p < NRP; p++) {
            mv[p] = g_prm[(size_t)p * NB * HW + idx];
            sv[p] = g_prs[(size_t)p * NB * HW + idx];
            m = fmaxf(m, mv[p]);
        }
        float s = 0.0f;
#pragma unroll
        for (int p = 0; p < NRP; p++)
            s += sv[p] * __expf(mv[p] - m);
        g_rmax[idx] = m;
        g_rinv[idx] = 1.0f / s;
    } else {
        float m = -CUDART_INF_F;
        float mv[NCP], sv[NCP];
#pragma unroll
        for (int p = 0; p < NCP; p++) {
            mv[p] = g_pcm[(size_t)p * NB * HW + idx];
            sv[p] = g_pcs[(size_t)p * NB * HW + idx];
            m = fmaxf(m, mv[p]);
        }
        float s = 0.0f;
#pragma unroll
        for (int p = 0; p < NCP; p++)
            s += sv[p] * __expf(mv[p] - m);
        g_cmax[idx] = m;
        g_cinv[idx] = 1.0f / s;
    }
}

// ---------------------------------------------------------------------------
// out[b][perm(j')][i] = exp(2L[i][j'] - rmax[i] - cmax[j']) * rinv[i]*cinv[j']
// perm(j') = (j'%32)*32 + j'/32
// ---------------------------------------------------------------------------
__global__ void out_kernel(float* __restrict__ out) {
    __shared__ float s[32][33];
    int b  = blockIdx.z;
    int i0 = blockIdx.y * 32;
    int j0 = blockIdx.x * 32;
    int tx = threadIdx.x;
    int ty = threadIdx.y;

    const float* Lp = g_L + (size_t)b * HW * HW;
#pragma unroll
    for (int r = 0; r < 4; r++) {
        int il = ty + r * 8;
        s[il][tx] = Lp[(size_t)(i0 + il) * HW + j0 + tx];
    }
    __syncthreads();

    int i = i0 + tx;
    float rm = g_rmax[b * HW + i];
    float ri = g_rinv[b * HW + i];
    float* op = out + (size_t)b * HW * HW;
#pragma unroll
    for (int r = 0; r < 4; r++) {
        int jl = ty + r * 8;
        int jn = j0 + jl;
        float cm = g_cmax[b * HW + jn];
        float ci = g_cinv[b * HW + jn];
        float v  = __expf(2.0f * s[tx][jl] - rm - cm) * (ri * ci);
        int j = ((jn & 31) << 5) | (jn >> 5);
        op[(size_t)j * HW + i] = v;
    }
}

// ---------------------------------------------------------------------------
extern "C" void kernel_launch(void* const* d_in, const int* in_sizes, int n_in,
                              void* d_out, int out_size) {
    const float* A  = (const float*)d_in[0];  // feature_A [32,256,32,32]
    const float* Bf = (const float*)d_in[1];  // feature_B [32,256,32,32]
    float* out = (float*)d_out;               // [32,1024,32,32]

    static int smem_set = 0;
    if (!smem_set) {
        cudaFuncSetAttribute(gemm_fused_kernel,
                             cudaFuncAttributeMaxDynamicSharedMemorySize,
                             GEMM_SMEM);
        smem_set = 1;
    }

    gemm_fused_kernel<<<dim3(8, 8, NB), 256, GEMM_SMEM>>>(A, Bf);
    combine_kernel<<<dim3((NB * HW + 255) / 256, 2), 256>>>();
    out_kernel<<<dim3(32, 32, NB), dim3(32, 8)>>>(out);
}

// round 8
// speedup vs baseline: 1.0650x; 1.0650x over previous
#include <cuda_runtime.h>
#include <math_constants.h>
#include <cstdint>

#define NB 32
#define NC 256
#define HW 1024
#define NRP 16          // row-partial slices (8 j-blocks x 2 wn)
#define NCP 32          // col-partial slices (8 i-blocks x 4 wm)

static __device__ __constant__ float c_invT = 14.2857142857142857f; // 1/0.07

// Fragment-ordered operands (tf32 values stored as f32 bits)
// M-side (feature_B, GEMM-A): [b][it16 64][kt8 32][lane 32][reg 4]
// N-side (feature_A*invT, GEMM-B): [b][jt8 128][kt8 32][lane 32][reg 2]
__device__ float g_MhiP[(size_t)NB * 64 * 32 * 128];
__device__ float g_MloP[(size_t)NB * 64 * 32 * 128];
__device__ float g_NhiP[(size_t)NB * 128 * 32 * 64];
__device__ float g_NloP[(size_t)NB * 128 * 32 * 64];
__device__ float g_L[(size_t)NB * HW * HW];
__device__ float g_rmax[NB * HW];
__device__ float g_rinv[NB * HW];
__device__ float g_cmax[NB * HW];
__device__ float g_cinv[NB * HW];
__device__ float g_prm[(size_t)NRP * NB * HW];
__device__ float g_prs[(size_t)NRP * NB * HW];
__device__ float g_pcm[(size_t)NCP * NB * HW];
__device__ float g_pcs[(size_t)NCP * NB * HW];

// ---- helpers --------------------------------------------------------------
__device__ __forceinline__ float tf32_rna(float x) {
    uint32_t r;
    asm("cvt.rna.tf32.f32 %0, %1;" : "=r"(r) : "f"(x));
    return __uint_as_float(r);
}
__device__ __forceinline__ uint32_t smem_u32(const void* p) {
    uint32_t a;
    asm("{ .reg .u64 t; cvta.to.shared.u64 t, %1; cvt.u32.u64 %0, t; }"
        : "=r"(a) : "l"(p));
    return a;
}
__device__ __forceinline__ void cp16(uint32_t sdst, const float* gsrc) {
    asm volatile("cp.async.cg.shared.global [%0], [%1], 16;"
                 :: "r"(sdst), "l"(gsrc) : "memory");
}
__device__ __forceinline__ void cp_commit() {
    asm volatile("cp.async.commit_group;" ::: "memory");
}
template <int N>
__device__ __forceinline__ void cp_wait() {
    asm volatile("cp.async.wait_group %0;" :: "n"(N) : "memory");
}
__device__ __forceinline__ void mma_tf32(float c[4], const uint32_t a[4],
                                         const uint32_t b[2]) {
    asm volatile(
        "mma.sync.aligned.m16n8k8.row.col.f32.tf32.tf32.f32 "
        "{%0,%1,%2,%3}, {%4,%5,%6,%7}, {%8,%9}, {%0,%1,%2,%3};"
        : "+f"(c[0]), "+f"(c[1]), "+f"(c[2]), "+f"(c[3])
        : "r"(a[0]), "r"(a[1]), "r"(a[2]), "r"(a[3]), "r"(b[0]), "r"(b[1]));
}

// ---------------------------------------------------------------------------
// Kernel 1: split + repack into HMMA fragment order.
// ---------------------------------------------------------------------------
__global__ void split_frag_kernel(const float* __restrict__ A,
                                  const float* __restrict__ Bf) {
    __shared__ float s[32][33];
    int zb   = blockIdx.z;          // side*NB + b
    int side = zb >> 5;
    int b    = zb & 31;
    int c0   = blockIdx.y * 32;
    int hw0  = blockIdx.x * 32;
    const float* src = (side ? A : Bf) + (size_t)b * NC * HW;
    int t    = threadIdx.x;
    int lane = t & 31;
    int g    = lane >> 2;
    int tig  = lane & 3;
    {
        int cr0 = t >> 5;
#pragma unroll
        for (int r = 0; r < 4; r++) {
            int cr = cr0 + r * 8;
            s[cr][lane] = src[(size_t)(c0 + cr) * HW + hw0 + lane];
        }
    }
    __syncthreads();

    if (side == 0) {
        int blk  = t >> 5;
        int it_l = blk >> 2;
        int kt_l = blk & 3;
        float hi[4], lo[4];
#pragma unroll
        for (int r = 0; r < 4; r++) {
            int row = it_l * 16 + g + 8 * (r & 1);
            int k   = kt_l * 8 + tig + 4 * (r >> 1);
            float v = s[k][row];
            hi[r] = tf32_rna(v);
            lo[r] = tf32_rna(v - hi[r]);
        }
        int it_g = (hw0 >> 4) + it_l;
        int kt_g = (c0 >> 3) + kt_l;
        size_t o = (((size_t)b * 64 + it_g) * 32 + kt_g) * 128 + lane * 4;
        *(float4*)(g_MhiP + o) = make_float4(hi[0], hi[1], hi[2], hi[3]);
        *(float4*)(g_MloP + o) = make_float4(lo[0], lo[1], lo[2], lo[3]);
    } else {
        int bb = t >> 5;
#pragma unroll
        for (int h = 0; h < 2; h++) {
            int blk  = bb + h * 8;
            int jt_l = blk & 3;
            int kt_l = blk >> 2;
            float hi[2], lo[2];
#pragma unroll
            for (int r = 0; r < 2; r++) {
                int row = jt_l * 8 + g;
                int k   = kt_l * 8 + tig + 4 * r;
                float v = s[k][row] * c_invT;
                hi[r] = tf32_rna(v);
                lo[r] = tf32_rna(v - hi[r]);
            }
            int jt_g = (hw0 >> 3) + jt_l;
            int kt_g = (c0 >> 3) + kt_l;
            size_t o = (((size_t)b * 128 + jt_g) * 32 + kt_g) * 64 + lane * 2;
            *(float2*)(g_NhiP + o) = make_float2(hi[0], hi[1]);
            *(float2*)(g_NloP + o) = make_float2(lo[0], lo[1]);
        }
    }
}

// ---------------------------------------------------------------------------
// Kernel 2: TF32 split GEMM on mma.sync + fused partial softmax stats.
// 2 CTAs/SM for latency hiding (128 regs, 2x32KB smem stages).
// ---------------------------------------------------------------------------
#define ACH_F 4096
#define BCH_F 4096
#define STG_F (ACH_F + BCH_F)
#define GEMM_SMEM (2 * STG_F * 4)

__device__ __forceinline__ void gemm_copy_chunk(uint32_t sA, uint32_t sB,
                                                const float* gA, const float* gB,
                                                int t) {
#pragma unroll
    for (int q = 0; q < 4; q++) {
        int f4 = q * 256 + t;
        int it = f4 >> 7, rema = f4 & 127;
        cp16(sA + (uint32_t)f4 * 16, gA + (size_t)it * 4096 + rema * 4);
        int jt = f4 >> 6, remb = f4 & 63;
        cp16(sB + (uint32_t)f4 * 16, gB + (size_t)jt * 2048 + remb * 4);
    }
    cp_commit();
}

__global__ void __launch_bounds__(256, 2) gemm_hmma_kernel() {
    extern __shared__ float sm[];
    uint32_t sbase = smem_u32(sm);
    int b   = blockIdx.z;
    int jt0 = blockIdx.x * 16;     // j0 = bx*128
    int it0 = blockIdx.y * 8;      // i0 = by*128
    int t    = threadIdx.x;
    int wid  = t >> 5;
    int lane = t & 31;
    int wm   = wid >> 1;
    int wn   = wid & 1;
    int g    = lane >> 2;
    int tig  = lane & 3;

    const float* MhiB = g_MhiP + ((size_t)b * 64 + it0) * 32 * 128;
    const float* MloB = g_MloP + ((size_t)b * 64 + it0) * 32 * 128;
    const float* NhiB = g_NhiP + ((size_t)b * 128 + jt0) * 32 * 64;
    const float* NloB = g_NloP + ((size_t)b * 128 + jt0) * 32 * 64;

    float acc[2][8][4];
#pragma unroll
    for (int m = 0; m < 2; m++)
#pragma unroll
        for (int n = 0; n < 8; n++)
#pragma unroll
            for (int r = 0; r < 4; r++) acc[m][n][r] = 0.0f;

    const float* gA;
    const float* gB;
#define CHUNK_PTRS(c)                                                       \
    {                                                                       \
        int term = (c) >> 3;                                                \
        int ko   = ((c) & 7) * 4;                                           \
        gA = (term == 2 ? MloB : MhiB) + (size_t)ko * 128;                  \
        gB = (term == 1 ? NloB : NhiB) + (size_t)ko * 64;                   \
    }

    CHUNK_PTRS(0);
    gemm_copy_chunk(sbase, sbase + ACH_F * 4, gA, gB, t);

    for (int c = 0; c < 24; c++) {
        int stage = c & 1;
        if (c + 1 < 24) {
            int ns = (c + 1) & 1;
            CHUNK_PTRS(c + 1);
            gemm_copy_chunk(sbase + ns * STG_F * 4,
                            sbase + (ns * STG_F + ACH_F) * 4, gA, gB, t);
            cp_wait<1>();
        } else {
            cp_wait<0>();
        }
        __syncthreads();

        const float* sA = sm + stage * STG_F;
        const float* sB = sA + ACH_F;
#pragma unroll
        for (int kt = 0; kt < 4; kt++) {
            uint32_t a[2][4];
#pragma unroll
            for (int m = 0; m < 2; m++) {
                int it = wm * 2 + m;
                float4 v = *(const float4*)(sA + it * 512 + kt * 128 + lane * 4);
                a[m][0] = __float_as_uint(v.x);
                a[m][1] = __float_as_uint(v.y);
                a[m][2] = __float_as_uint(v.z);
                a[m][3] = __float_as_uint(v.w);
            }
            uint32_t bf[8][2];
#pragma unroll
            for (int n = 0; n < 8; n++) {
                int jt = wn * 8 + n;
                float2 v = *(const float2*)(sB + jt * 256 + kt * 64 + lane * 2);
                bf[n][0] = __float_as_uint(v.x);
                bf[n][1] = __float_as_uint(v.y);
            }
#pragma unroll
            for (int m = 0; m < 2; m++)
#pragma unroll
                for (int n = 0; n < 8; n++)
                    mma_tf32(acc[m][n], a[m], bf[n]);
        }
        __syncthreads();
    }

    // ---- store L tile ----
    float* Lp = g_L + (size_t)b * HW * HW;
    int j0 = jt0 * 8;
    int i0 = it0 * 16;
#pragma unroll
    for (int m = 0; m < 2; m++) {
        int row0 = i0 + (wm * 2 + m) * 16 + g;
#pragma unroll
        for (int n = 0; n < 8; n++) {
            int col = j0 + (wn * 8 + n) * 8 + tig * 2;
            *(float2*)(Lp + (size_t)row0 * HW + col) =
                make_float2(acc[m][n][0], acc[m][n][1]);
            *(float2*)(Lp + (size_t)(row0 + 8) * HW + col) =
                make_float2(acc[m][n][2], acc[m][n][3]);
        }
    }

    // ---- fused row partials (over this warp's 64 j's) ----
    int rslice = blockIdx.x * 2 + wn;       // 0..15
#pragma unroll
    for (int m = 0; m < 2; m++)
#pragma unroll
        for (int rp = 0; rp < 2; rp++) {
            float rm = -CUDART_INF_F;
#pragma unroll
            for (int n = 0; n < 8; n++)
                rm = fmaxf(rm, fmaxf(acc[m][n][rp * 2], acc[m][n][rp * 2 + 1]));
            rm = fmaxf(rm, __shfl_xor_sync(0xFFFFFFFFu, rm, 1));
            rm = fmaxf(rm, __shfl_xor_sync(0xFFFFFFFFu, rm, 2));
            float rs = 0.0f;
#pragma unroll
            for (int n = 0; n < 8; n++)
                rs += __expf(acc[m][n][rp * 2] - rm) +
                      __expf(acc[m][n][rp * 2 + 1] - rm);
            rs += __shfl_xor_sync(0xFFFFFFFFu, rs, 1);
            rs += __shfl_xor_sync(0xFFFFFFFFu, rs, 2);
            if (tig == 0) {
                int i = i0 + wm * 32 + m * 16 + rp * 8 + g;
                size_t idx = (size_t)rslice * NB * HW + b * HW + i;
                g_prm[idx] = rm;
                g_prs[idx] = rs;
            }
        }

    // ---- fused col partials (over this warp's 32 i's) ----
    int cslice = blockIdx.y * 4 + wm;       // 0..31
#pragma unroll
    for (int n = 0; n < 8; n++)
#pragma unroll
        for (int q = 0; q < 2; q++) {
            float cm = fmaxf(fmaxf(acc[0][n][q], acc[0][n][2 + q]),
                             fmaxf(acc[1][n][q], acc[1][n][2 + q]));
            cm = fmaxf(cm, __shfl_xor_sync(0xFFFFFFFFu, cm, 4));
            cm = fmaxf(cm, __shfl_xor_sync(0xFFFFFFFFu, cm, 8));
            cm = fmaxf(cm, __shfl_xor_sync(0xFFFFFFFFu, cm, 16));
            float cs = __expf(acc[0][n][q] - cm) + __expf(acc[0][n][2 + q] - cm) +
                       __expf(acc[1][n][q] - cm) + __expf(acc[1][n][2 + q] - cm);
            cs += __shfl_xor_sync(0xFFFFFFFFu, cs, 4);
            cs += __shfl_xor_sync(0xFFFFFFFFu, cs, 8);
            cs += __shfl_xor_sync(0xFFFFFFFFu, cs, 16);
            if (g == 0) {
                int j = j0 + wn * 64 + n * 8 + tig * 2 + q;
                size_t idx = (size_t)cslice * NB * HW + b * HW + j;
                g_pcm[idx] = cm;
                g_pcs[idx] = cs;
            }
        }
}

// ---------------------------------------------------------------------------
// Combine kernel: blockIdx.y==0 -> row partials (16), ==1 -> col partials (32)
// ---------------------------------------------------------------------------
__global__ void combine_kernel() {
    int idx = blockIdx.x * 256 + threadIdx.x;
    if (idx >= NB * HW) return;
    if (blockIdx.y == 0) {
        float m = -CUDART_INF_F;
        float mv[NRP], sv[NRP];
#pragma unroll
        for (int p = 0; p < NRP; p++) {
            mv[p] = g_prm[(size_t)p * NB * HW + idx];
            sv[p] = g_prs[(size_t)p * NB * HW + idx];
            m = fmaxf(m, mv[p]);
        }
        float s = 0.0f;
#pragma unroll
        for (int p = 0; p < NRP; p++)
            s += sv[p] * __expf(mv[p] - m);
        g_rmax[idx] = m;
        g_rinv[idx] = 1.0f / s;
    } else {
        float m = -CUDART_INF_F;
        float mv[NCP], sv[NCP];
#pragma unroll
        for (int p = 0; p < NCP; p++) {
            mv[p] = g_pcm[(size_t)p * NB * HW + idx];
            sv[p] = g_pcs[(size_t)p * NB * HW + idx];
            m = fmaxf(m, mv[p]);
        }
        float s = 0.0f;
#pragma unroll
        for (int p = 0; p < NCP; p++)
            s += sv[p] * __expf(mv[p] - m);
        g_cmax[idx] = m;
        g_cinv[idx] = 1.0f / s;
    }
}

// ---------------------------------------------------------------------------
// out[b][perm(j')][i] = exp(2L[i][j'] - rmax[i] - cmax[j']) * rinv[i]*cinv[j']
// perm(j') = (j'%32)*32 + j'/32
// ---------------------------------------------------------------------------
__global__ void out_kernel(float* __restrict__ out) {
    __shared__ float s[32][33];
    int b  = blockIdx.z;
    int i0 = blockIdx.y * 32;
    int j0 = blockIdx.x * 32;
    int tx = threadIdx.x;
    int ty = threadIdx.y;

    const float* Lp = g_L + (size_t)b * HW * HW;
#pragma unroll
    for (int r = 0; r < 4; r++) {
        int il = ty + r * 8;
        s[il][tx] = Lp[(size_t)(i0 + il) * HW + j0 + tx];
    }
    __syncthreads();

    int i = i0 + tx;
    float rm = g_rmax[b * HW + i];
    float ri = g_rinv[b * HW + i];
    float* op = out + (size_t)b * HW * HW;
#pragma unroll
    for (int r = 0; r < 4; r++) {
        int jl = ty + r * 8;
        int jn = j0 + jl;
        float cm = g_cmax[b * HW + jn];
        float ci = g_cinv[b * HW + jn];
        float v  = __expf(2.0f * s[tx][jl] - rm - cm) * (ri * ci);
        int j = ((jn & 31) << 5) | (jn >> 5);
        op[(size_t)j * HW + i] = v;
    }
}

// ---------------------------------------------------------------------------
extern "C" void kernel_launch(void* const* d_in, const int* in_sizes, int n_in,
                              void* d_out, int out_size) {
    const float* A  = (const float*)d_in[0];  // feature_A [32,256,32,32]
    const float* Bf = (const float*)d_in[1];  // feature_B [32,256,32,32]
    float* out = (float*)d_out;               // [32,1024,32,32]

    static int smem_set = 0;
    if (!smem_set) {
        cudaFuncSetAttribute(gemm_hmma_kernel,
                             cudaFuncAttributeMaxDynamicSharedMemorySize,
                             GEMM_SMEM);
        smem_set = 1;
    }

    split_frag_kernel<<<dim3(32, 8, 2 * NB), 256>>>(A, Bf);
    gemm_hmma_kernel<<<dim3(8, 8, NB), 256, GEMM_SMEM>>>();
    combine_kernel<<<dim3((NB * HW + 255) / 256, 2), 256>>>();
    out_kernel<<<dim3(32, 32, NB), dim3(32, 8)>>>(out);
}

// round 9
// speedup vs baseline: 1.3381x; 1.2564x over previous
#include <cuda_runtime.h>
#include <cuda_bf16.h>
#include <math_constants.h>
#include <cstdint>

#define NB 32
#define NC 256
#define HW 1024
#define NRP 16          // row-partial slices
#define NCP 32          // col-partial slices

static __device__ __constant__ float c_invT = 14.2857142857142857f; // 1/0.07

// Fragment-ordered operands:
// MhiP: tf32 hi, GEMM-A (feature_B): [b][it16 64][kt8 32][lane 32][4] f32
// NhiP: tf32 hi, GEMM-B (feature_A*invT): [b][jt8 128][kt8 32][lane 32][2] f32
// MbfP: bf16x2 cross A' = [hi(vkt<16) | lo(vkt>=16)]: [b][it 64][vkt 32][lane][4] u32
// NbfP: bf16x2 cross B' = [lo(vkt<16) | hi(vkt>=16)]: [b][jt 128][vkt 32][lane][2] u32
__device__ float    g_MhiP[(size_t)NB * 64 * 32 * 128];
__device__ float    g_NhiP[(size_t)NB * 128 * 32 * 64];
__device__ uint32_t g_MbfP[(size_t)NB * 64 * 32 * 128];
__device__ uint32_t g_NbfP[(size_t)NB * 128 * 32 * 64];
__device__ float g_L[(size_t)NB * HW * HW];
__device__ float g_rmax[NB * HW];
__device__ float g_rinv[NB * HW];
__device__ float g_cmax[NB * HW];
__device__ float g_cinv[NB * HW];
__device__ float g_prm[(size_t)NRP * NB * HW];
__device__ float g_prs[(size_t)NRP * NB * HW];
__device__ float g_pcm[(size_t)NCP * NB * HW];
__device__ float g_pcs[(size_t)NCP * NB * HW];

// ---- helpers --------------------------------------------------------------
__device__ __forceinline__ float tf32_rna(float x) {
    uint32_t r;
    asm("cvt.rna.tf32.f32 %0, %1;" : "=r"(r) : "f"(x));
    return __uint_as_float(r);
}
__device__ __forceinline__ uint32_t bf2pack(float x, float y) {
    uint16_t lx = __bfloat16_as_ushort(__float2bfloat16(x));
    uint16_t ly = __bfloat16_as_ushort(__float2bfloat16(y));
    return ((uint32_t)ly << 16) | (uint32_t)lx;
}
__device__ __forceinline__ uint32_t smem_u32(const void* p) {
    uint32_t a;
    asm("{ .reg .u64 t; cvta.to.shared.u64 t, %1; cvt.u32.u64 %0, t; }"
        : "=r"(a) : "l"(p));
    return a;
}
__device__ __forceinline__ void cp16(uint32_t sdst, const void* gsrc) {
    asm volatile("cp.async.cg.shared.global [%0], [%1], 16;"
                 :: "r"(sdst), "l"(gsrc) : "memory");
}
__device__ __forceinline__ void cp_commit() {
    asm volatile("cp.async.commit_group;" ::: "memory");
}
template <int N>
__device__ __forceinline__ void cp_wait() {
    asm volatile("cp.async.wait_group %0;" :: "n"(N) : "memory");
}
__device__ __forceinline__ void mma_tf32(float c[4], const uint32_t a[4],
                                         const uint32_t b[2]) {
    asm volatile(
        "mma.sync.aligned.m16n8k8.row.col.f32.tf32.tf32.f32 "
        "{%0,%1,%2,%3}, {%4,%5,%6,%7}, {%8,%9}, {%0,%1,%2,%3};"
        : "+f"(c[0]), "+f"(c[1]), "+f"(c[2]), "+f"(c[3])
        : "r"(a[0]), "r"(a[1]), "r"(a[2]), "r"(a[3]), "r"(b[0]), "r"(b[1]));
}
__device__ __forceinline__ void mma_bf16(float c[4], const uint32_t a[4],
                                         const uint32_t b[2]) {
    asm volatile(
        "mma.sync.aligned.m16n8k16.row.col.f32.bf16.bf16.f32 "
        "{%0,%1,%2,%3}, {%4,%5,%6,%7}, {%8,%9}, {%0,%1,%2,%3};"
        : "+f"(c[0]), "+f"(c[1]), "+f"(c[2]), "+f"(c[3])
        : "r"(a[0]), "r"(a[1]), "r"(a[2]), "r"(a[3]), "r"(b[0]), "r"(b[1]));
}

// ---------------------------------------------------------------------------
// Kernel 1: split + repack (tf32 hi frags + bf16 cross frags).
// grid: (hw/32, c/32, 2*NB), block 256.
// ---------------------------------------------------------------------------
__global__ void split_frag_kernel(const float* __restrict__ A,
                                  const float* __restrict__ Bf) {
    __shared__ float s[32][33];
    int zb   = blockIdx.z;
    int side = zb >> 5;
    int b    = zb & 31;
    int c0   = blockIdx.y * 32;
    int hw0  = blockIdx.x * 32;
    const float* src = (side ? A : Bf) + (size_t)b * NC * HW;
    int t    = threadIdx.x;
    int lane = t & 31;
    int g    = lane >> 2;
    int tig  = lane & 3;
    int blk  = t >> 5;
    {
#pragma unroll
        for (int r = 0; r < 4; r++) {
            int cr = blk + r * 8;
            s[cr][lane] = src[(size_t)(c0 + cr) * HW + hw0 + lane];
        }
    }
    __syncthreads();

    if (side == 0) {
        // --- tf32 hi frags: 8 units (it_l 2 x kt8_l 4) ---
        {
            int it_l = blk >> 2, kt8_l = blk & 3;
            float hi[4];
#pragma unroll
            for (int r = 0; r < 4; r++) {
                int row = it_l * 16 + g + 8 * (r & 1);
                int k   = kt8_l * 8 + tig + 4 * (r >> 1);
                hi[r] = tf32_rna(s[k][row]);
            }
            int it_g = (hw0 >> 4) + it_l;
            int kt_g = (c0 >> 3) + kt8_l;
            size_t o = (((size_t)b * 64 + it_g) * 32 + kt_g) * 128 + lane * 4;
            *(float4*)(g_MhiP + o) = make_float4(hi[0], hi[1], hi[2], hi[3]);
        }
        // --- bf16 frags: 4 units (it_l 2 x kt16_l 2), h = hi/lo ---
        {
            int u = blk >> 1, h = blk & 1;
            int it_l = u >> 1, kt16_l = u & 1;
            uint32_t pk[4];
#pragma unroll
            for (int r = 0; r < 4; r++) {
                int row = it_l * 16 + g + 8 * (r & 1);
                int kb  = kt16_l * 16 + 2 * tig + 8 * (r >> 1);
                float v0 = s[kb][row], v1 = s[kb + 1][row];
                float h0 = tf32_rna(v0), h1 = tf32_rna(v1);
                pk[r] = h ? bf2pack(v0 - h0, v1 - h1) : bf2pack(h0, h1);
            }
            int it_g = (hw0 >> 4) + it_l;
            int vkt  = (h ? 16 : 0) + (c0 >> 4) + kt16_l;  // A': hi low, lo high
            size_t o = (((size_t)b * 64 + it_g) * 32 + vkt) * 128 + lane * 4;
            *(uint4*)(g_MbfP + o) = make_uint4(pk[0], pk[1], pk[2], pk[3]);
        }
    } else {
        // --- tf32 hi frags: 16 units (jt_l 4 x kt8_l 4), 2 per warp ---
#pragma unroll
        for (int h = 0; h < 2; h++) {
            int u = blk + h * 8;
            int jt_l = u & 3, kt8_l = u >> 2;
            float hi[2];
#pragma unroll
            for (int r = 0; r < 2; r++) {
                int row = jt_l * 8 + g;
                int k   = kt8_l * 8 + tig + 4 * r;
                hi[r] = tf32_rna(s[k][row] * c_invT);
            }
            int jt_g = (hw0 >> 3) + jt_l;
            int kt_g = (c0 >> 3) + kt8_l;
            size_t o = (((size_t)b * 128 + jt_g) * 32 + kt_g) * 64 + lane * 2;
            *(float2*)(g_NhiP + o) = make_float2(hi[0], hi[1]);
        }
        // --- bf16 frags: 8 units (jt_l 4 x kt16_l 2), write lo+hi entries ---
        {
            int jt_l = blk & 3, kt16_l = blk >> 2;
            uint32_t ph[2], pl[2];
#pragma unroll
            for (int r = 0; r < 2; r++) {
                int row = jt_l * 8 + g;
                int kb  = kt16_l * 16 + 2 * tig + 8 * r;
                float v0 = s[kb][row] * c_invT, v1 = s[kb + 1][row] * c_invT;
                float h0 = tf32_rna(v0), h1 = tf32_rna(v1);
                ph[r] = bf2pack(h0, h1);
                pl[r] = bf2pack(v0 - h0, v1 - h1);
            }
            int jt_g = (hw0 >> 3) + jt_l;
            int ckt  = (c0 >> 4) + kt16_l;
            size_t base = ((size_t)b * 128 + jt_g) * 32;
            // B': lo in vkt<16, hi in vkt>=16
            *(uint2*)(g_NbfP + (base + ckt) * 64 + lane * 2)        = make_uint2(pl[0], pl[1]);
            *(uint2*)(g_NbfP + (base + 16 + ckt) * 64 + lane * 2)   = make_uint2(ph[0], ph[1]);
        }
    }
}

// ---------------------------------------------------------------------------
// Kernel 2: mixed tf32-hi + bf16-cross GEMM + fused partial softmax stats.
// 16 chunks (kt16), 32KB/stage double-buffered, 2 CTAs/SM.
// Stage layout (words): [0,2048) Ahi | [2048,4096) Bhi | [4096,6144) Abf | [6144,8192) Bbf
// ---------------------------------------------------------------------------
#define STG_W 8192
#define GEMM_SMEM (2 * STG_W * 4)   // 65536 bytes

__device__ __forceinline__ void copy_chunk(uint32_t sbase, int ck,
                                           const float* MhiB, const uint32_t* MbfB,
                                           const float* NhiB, const uint32_t* NbfB,
                                           int t) {
#pragma unroll
    for (int q = 0; q < 2; q++) {   // Ahi: 512 quads
        int f4 = t + q * 256;
        int it = f4 >> 6, rem = f4 & 63;
        cp16(sbase + (uint32_t)f4 * 16, MhiB + (size_t)it * 4096 + ck * 256 + rem * 4);
    }
#pragma unroll
    for (int q = 0; q < 2; q++) {   // Bhi
        int f4 = t + q * 256;
        int jt = f4 >> 5, rem = f4 & 31;
        cp16(sbase + 8192 + (uint32_t)f4 * 16, NhiB + (size_t)jt * 2048 + ck * 128 + rem * 4);
    }
#pragma unroll
    for (int q = 0; q < 2; q++) {   // Abf
        int f4 = t + q * 256;
        int it = f4 >> 6, half = (f4 >> 5) & 1, rem = f4 & 31;
        cp16(sbase + 16384 + (uint32_t)f4 * 16,
             MbfB + (size_t)it * 4096 + (ck + half * 16) * 128 + rem * 4);
    }
#pragma unroll
    for (int q = 0; q < 2; q++) {   // Bbf
        int f4 = t + q * 256;
        int jt = f4 >> 5, half = (f4 >> 4) & 1, rem = f4 & 15;
        cp16(sbase + 24576 + (uint32_t)f4 * 16,
             NbfB + (size_t)jt * 2048 + (ck + half * 16) * 64 + rem * 4);
    }
    cp_commit();
}

__global__ void __launch_bounds__(256, 2) gemm_hmma_kernel() {
    extern __shared__ float sm[];
    uint32_t sbase = smem_u32(sm);
    int b   = blockIdx.z;
    int jt0 = blockIdx.x * 16;     // j0 = bx*128
    int it0 = blockIdx.y * 8;      // i0 = by*128
    int t    = threadIdx.x;
    int wid  = t >> 5;
    int lane = t & 31;
    int wm   = wid >> 1;
    int wn   = wid & 1;
    int g    = lane >> 2;
    int tig  = lane & 3;

    const float*    MhiB = g_MhiP + ((size_t)b * 64 + it0) * 4096;
    const uint32_t* MbfB = g_MbfP + ((size_t)b * 64 + it0) * 4096;
    const float*    NhiB = g_NhiP + ((size_t)b * 128 + jt0) * 2048;
    const uint32_t* NbfB = g_NbfP + ((size_t)b * 128 + jt0) * 2048;

    float acc[2][8][4];
#pragma unroll
    for (int m = 0; m < 2; m++)
#pragma unroll
        for (int n = 0; n < 8; n++)
#pragma unroll
            for (int r = 0; r < 4; r++) acc[m][n][r] = 0.0f;

    copy_chunk(sbase, 0, MhiB, MbfB, NhiB, NbfB, t);

    for (int c = 0; c < 16; c++) {
        int stage = c & 1;
        if (c + 1 < 16) {
            copy_chunk(sbase + ((c + 1) & 1) * STG_W * 4, c + 1,
                       MhiB, MbfB, NhiB, NbfB, t);
            cp_wait<1>();
        } else {
            cp_wait<0>();
        }
        __syncthreads();

        const float* sA = sm + stage * STG_W;
        const uint32_t* sAu = (const uint32_t*)sA;
        // tf32 hi terms
#pragma unroll
        for (int k8 = 0; k8 < 2; k8++) {
            uint32_t a[2][4];
#pragma unroll
            for (int m = 0; m < 2; m++) {
                float4 v = *(const float4*)(sA + (wm * 2 + m) * 256 + k8 * 128 + lane * 4);
                a[m][0] = __float_as_uint(v.x); a[m][1] = __float_as_uint(v.y);
                a[m][2] = __float_as_uint(v.z); a[m][3] = __float_as_uint(v.w);
            }
            uint32_t bf[8][2];
#pragma unroll
            for (int n = 0; n < 8; n++) {
                float2 v = *(const float2*)(sA + 2048 + (wn * 8 + n) * 128 + k8 * 64 + lane * 2);
                bf[n][0] = __float_as_uint(v.x); bf[n][1] = __float_as_uint(v.y);
            }
#pragma unroll
            for (int m = 0; m < 2; m++)
#pragma unroll
                for (int n = 0; n < 8; n++)
                    mma_tf32(acc[m][n], a[m], bf[n]);
        }
        // bf16 cross terms
#pragma unroll
        for (int half = 0; half < 2; half++) {
            uint32_t a[2][4];
#pragma unroll
            for (int m = 0; m < 2; m++) {
                uint4 v = *(const uint4*)(sAu + 4096 + (wm * 2 + m) * 256 + half * 128 + lane * 4);
                a[m][0] = v.x; a[m][1] = v.y; a[m][2] = v.z; a[m][3] = v.w;
            }
            uint32_t bf[8][2];
#pragma unroll
            for (int n = 0; n < 8; n++) {
                uint2 v = *(const uint2*)(sAu + 6144 + (wn * 8 + n) * 128 + half * 64 + lane * 2);
                bf[n][0] = v.x; bf[n][1] = v.y;
            }
#pragma unroll
            for (int m = 0; m < 2; m++)
#pragma unroll
                for (int n = 0; n < 8; n++)
                    mma_bf16(acc[m][n], a[m], bf[n]);
        }
        __syncthreads();
    }

    // ---- store L tile ----
    float* Lp = g_L + (size_t)b * HW * HW;
    int j0 = jt0 * 8;
    int i0 = it0 * 16;
#pragma unroll
    for (int m = 0; m < 2; m++) {
        int row0 = i0 + (wm * 2 + m) * 16 + g;
#pragma unroll
        for (int n = 0; n < 8; n++) {
            int col = j0 + (wn * 8 + n) * 8 + tig * 2;
            *(float2*)(Lp + (size_t)row0 * HW + col) =
                make_float2(acc[m][n][0], acc[m][n][1]);
            *(float2*)(Lp + (size_t)(row0 + 8) * HW + col) =
                make_float2(acc[m][n][2], acc[m][n][3]);
        }
    }

    // ---- fused row partials ----
    int rslice = blockIdx.x * 2 + wn;
#pragma unroll
    for (int m = 0; m < 2; m++)
#pragma unroll
        for (int rp = 0; rp < 2; rp++) {
            float rm = -CUDART_INF_F;
#pragma unroll
            for (int n = 0; n < 8; n++)
                rm = fmaxf(rm, fmaxf(acc[m][n][rp * 2], acc[m][n][rp * 2 + 1]));
            rm = fmaxf(rm, __shfl_xor_sync(0xFFFFFFFFu, rm, 1));
            rm = fmaxf(rm, __shfl_xor_sync(0xFFFFFFFFu, rm, 2));
            float rs = 0.0f;
#pragma unroll
            for (int n = 0; n < 8; n++)
                rs += __expf(acc[m][n][rp * 2] - rm) +
                      __expf(acc[m][n][rp * 2 + 1] - rm);
            rs += __shfl_xor_sync(0xFFFFFFFFu, rs, 1);
            rs += __shfl_xor_sync(0xFFFFFFFFu, rs, 2);
            if (tig == 0) {
                int i = i0 + wm * 32 + m * 16 + rp * 8 + g;
                size_t idx = (size_t)rslice * NB * HW + b * HW + i;
                g_prm[idx] = rm;
                g_prs[idx] = rs;
            }
        }

    // ---- fused col partials ----
    int cslice = blockIdx.y * 4 + wm;
#pragma unroll
    for (int n = 0; n < 8; n++)
#pragma unroll
        for (int q = 0; q < 2; q++) {
            float cm = fmaxf(fmaxf(acc[0][n][q], acc[0][n][2 + q]),
                             fmaxf(acc[1][n][q], acc[1][n][2 + q]));
            cm = fmaxf(cm, __shfl_xor_sync(0xFFFFFFFFu, cm, 4));
            cm = fmaxf(cm, __shfl_xor_sync(0xFFFFFFFFu, cm, 8));
            cm = fmaxf(cm, __shfl_xor_sync(0xFFFFFFFFu, cm, 16));
            float cs = __expf(acc[0][n][q] - cm) + __expf(acc[0][n][2 + q] - cm) +
                       __expf(acc[1][n][q] - cm) + __expf(acc[1][n][2 + q] - cm);
            cs += __shfl_xor_sync(0xFFFFFFFFu, cs, 4);
            cs += __shfl_xor_sync(0xFFFFFFFFu, cs, 8);
            cs += __shfl_xor_sync(0xFFFFFFFFu, cs, 16);
            if (g == 0) {
                int j = j0 + wn * 64 + n * 8 + tig * 2 + q;
                size_t idx = (size_t)cslice * NB * HW + b * HW + j;
                g_pcm[idx] = cm;
                g_pcs[idx] = cs;
            }
        }
}

// ---------------------------------------------------------------------------
// Combine kernel: y==0 -> row partials (16), y==1 -> col partials (32)
// ---------------------------------------------------------------------------
__global__ void combine_kernel() {
    int idx = blockIdx.x * 256 + threadIdx.x;
    if (idx >= NB * HW) return;
    if (blockIdx.y == 0) {
        float m = -CUDART_INF_F;
        float mv[NRP], sv[NRP];
#pragma unroll
        for (int p = 0; p < NRP; p++) {
            mv[p] = g_prm[(size_t)p * NB * HW + idx];
            sv[p] = g_prs[(size_t)p * NB * HW + idx];
            m = fmaxf(m, mv[p]);
        }
        float s = 0.0f;
#pragma unroll
        for (int p = 0; p < NRP; p++)
            s += sv[p] * __expf(mv[p] - m);
        g_rmax[idx] = m;
        g_rinv[idx] = 1.0f / s;
    } else {
        float m = -CUDART_INF_F;
        float mv[NCP], sv[NCP];
#pragma unroll
        for (int p = 0; p < NCP; p++) {
            mv[p] = g_pcm[(size_t)p * NB * HW + idx];
            sv[p] = g_pcs[(size_t)p * NB * HW + idx];
            m = fmaxf(m, mv[p]);
        }
        float s = 0.0f;
#pragma unroll
        for (int p = 0; p < NCP; p++)
            s += sv[p] * __expf(mv[p] - m);
        g_cmax[idx] = m;
        g_cinv[idx] = 1.0f / s;
    }
}

// ---------------------------------------------------------------------------
// out[b][perm(j')][i] = exp(2L[i][j'] - rmax[i] - cmax[j']) * rinv[i]*cinv[j']
// Vectorized: float4 IO, conflict-free smem transpose.
// ---------------------------------------------------------------------------
__global__ void out_kernel(float* __restrict__ out) {
    __shared__ float s[32][33];
    int b  = blockIdx.z;
    int i0 = blockIdx.y * 32;
    int j0 = blockIdx.x * 32;
    int t  = threadIdx.x;

    const float* Lp = g_L + (size_t)b * HW * HW;
    {
        int row = t >> 3, c4 = (t & 7) * 4;
        float4 v = *(const float4*)(Lp + (size_t)(i0 + row) * HW + j0 + c4);
        s[row][c4 + 0] = v.x; s[row][c4 + 1] = v.y;
        s[row][c4 + 2] = v.z; s[row][c4 + 3] = v.w;
    }
    __syncthreads();

    int jrow = t >> 3;
    int ib   = (t & 7) * 4;
    int jn   = j0 + jrow;
    float cm = g_cmax[b * HW + jn];
    float ci = g_cinv[b * HW + jn];
    float4 rmv = *(const float4*)(g_rmax + b * HW + i0 + ib);
    float4 riv = *(const float4*)(g_rinv + b * HW + i0 + ib);
    float4 o;
    o.x = __expf(2.0f * s[ib + 0][jrow] - rmv.x - cm) * riv.x * ci;
    o.y = __expf(2.0f * s[ib + 1][jrow] - rmv.y - cm) * riv.y * ci;
    o.z = __expf(2.0f * s[ib + 2][jrow] - rmv.z - cm) * riv.z * ci;
    o.w = __expf(2.0f * s[ib + 3][jrow] - rmv.w - cm) * riv.w * ci;
    int j = ((jn & 31) << 5) | (jn >> 5);
    *(float4*)(out + ((size_t)b * HW + j) * HW + i0 + ib) = o;
}

// ---------------------------------------------------------------------------
extern "C" void kernel_launch(void* const* d_in, const int* in_sizes, int n_in,
                              void* d_out, int out_size) {
    const float* A  = (const float*)d_in[0];  // feature_A [32,256,32,32]
    const float* Bf = (const float*)d_in[1];  // feature_B [32,256,32,32]
    float* out = (float*)d_out;               // [32,1024,32,32]

    static int smem_set = 0;
    if (!smem_set) {
        cudaFuncSetAttribute(gemm_hmma_kernel,
                             cudaFuncAttributeMaxDynamicSharedMemorySize,
                             GEMM_SMEM);
        smem_set = 1;
    }

    split_frag_kernel<<<dim3(32, 8, 2 * NB), 256>>>(A, Bf);
    gemm_hmma_kernel<<<dim3(8, 8, NB), 256, GEMM_SMEM>>>();
    combine_kernel<<<dim3((NB * HW + 255) / 256, 2), 256>>>();
    out_kernel<<<dim3(32, 32, NB), 256>>>(out);
}